// round 12
// baseline (speedup 1.0000x reference)
#include <cuda_runtime.h>
#include <cstdint>

#define BSZ    4096
#define HEADS  4
#define HALF   256
#define NKEYS  512
#define KNN    32
#define VDIM   1024
#define INDIM  1024
#define QCOLS  2048      // HEADS * K_DIM = 4*512

// ---- scratch (device globals: allocation-free) ----
__device__ float g_q[(size_t)BSZ * QCOLS];               // 32 MB
__device__ float g_scores[(size_t)8 * BSZ * NKEYS];      // 64 MB : [hs][b][n]
__device__ float g_w[(size_t)BSZ * HEADS * KNN];         // 2 MB
__device__ int   g_idx[(size_t)BSZ * HEADS * KNN];       // 2 MB

// ============================================================================
// Kernel 1: q = x @ Wq   (M=4096, N=2048, K=1024)  NN, fp32.
//   512 threads, CTA tile 128x128, ktile 16, per-thread 4x8 (32 accs).
//   Double-buffered smem + register prefetch. Per-element k-order identical
//   to the proven R5 kernel -> bit-identical output.
// ============================================================================
__global__ void __launch_bounds__(512, 2) q_gemm(const float* __restrict__ A,
                                                 const float* __restrict__ B) {
    const int N = QCOLS;
    const int K = INDIM;
    __shared__ float As[2][16][128];
    __shared__ float Bs[2][16][128];

    const int tid = threadIdx.x;
    const float* Ab = A + (size_t)blockIdx.y * 128 * INDIM;
    const float* Bb = B + blockIdx.x * 128;

    // loads: one float4 each for A and B per thread
    const int a_row = tid >> 2;                  // 0..127
    const int a_kq  = (tid & 3) * 4;             // 0,4,8,12
    const int b_kr  = tid >> 5;                  // 0..15
    const int b_cq  = (tid & 31) * 4;            // 0..124

    // compute mapping: 4 rows x 8 cols per thread
    const int cx = (tid & 15) * 8;               // col base
    const int ry = (tid >> 4) * 4;               // row base

    float acc[4][8];
    #pragma unroll
    for (int i = 0; i < 4; i++)
        #pragma unroll
        for (int j = 0; j < 8; j++) acc[i][j] = 0.f;

    float4 ra, rb;

    // prologue: tile 0 -> regs -> smem[0]
    ra = *(const float4*)(Ab + (size_t)a_row * INDIM + a_kq);
    rb = *(const float4*)(Bb + (size_t)b_kr * N + b_cq);
    As[0][a_kq + 0][a_row] = ra.x; As[0][a_kq + 1][a_row] = ra.y;
    As[0][a_kq + 2][a_row] = ra.z; As[0][a_kq + 3][a_row] = ra.w;
    *(float4*)&Bs[0][b_kr][b_cq] = rb;
    __syncthreads();

    const int ntiles = K / 16;
    for (int t = 0; t < ntiles; t++) {
        const int cur = t & 1;
        if (t + 1 < ntiles) {
            const int k0 = (t + 1) * 16;
            ra = *(const float4*)(Ab + (size_t)a_row * INDIM + k0 + a_kq);
            rb = *(const float4*)(Bb + (size_t)(k0 + b_kr) * N + b_cq);
        }

        #pragma unroll
        for (int kk = 0; kk < 16; kk++) {
            float4 av = *(float4*)&As[cur][kk][ry];
            float4 b0 = *(float4*)&Bs[cur][kk][cx];
            float4 b1 = *(float4*)&Bs[cur][kk][cx + 4];
            float a[4] = {av.x, av.y, av.z, av.w};
            float b[8] = {b0.x, b0.y, b0.z, b0.w, b1.x, b1.y, b1.z, b1.w};
            #pragma unroll
            for (int i = 0; i < 4; i++)
                #pragma unroll
                for (int j = 0; j < 8; j++) acc[i][j] += a[i] * b[j];
        }

        if (t + 1 < ntiles) {
            const int nxt = cur ^ 1;
            As[nxt][a_kq + 0][a_row] = ra.x; As[nxt][a_kq + 1][a_row] = ra.y;
            As[nxt][a_kq + 2][a_row] = ra.z; As[nxt][a_kq + 3][a_row] = ra.w;
            *(float4*)&Bs[nxt][b_kr][b_cq] = rb;
            __syncthreads();
        }
    }

    #pragma unroll
    for (int i = 0; i < 4; i++) {
        float* Cp = g_q + (size_t)(blockIdx.y * 128 + ry + i) * N + blockIdx.x * 128 + cx;
        *(float4*)(Cp)     = make_float4(acc[i][0], acc[i][1], acc[i][2], acc[i][3]);
        *(float4*)(Cp + 4) = make_float4(acc[i][4], acc[i][5], acc[i][6], acc[i][7]);
    }
}

// ============================================================================
// Kernel 2: scores[hs][b][n] = sum_d q[b, hs*256+d] * keys[hs][n][d]  (NT)
//   per hs: M=4096, N=512, K=256. grid=(4,32,8). 512 threads, 4x8 tile.
// ============================================================================
__global__ void __launch_bounds__(512, 2) score_gemm(const float* __restrict__ keys) {
    const int hs = blockIdx.z;
    const float* Ab = g_q + hs * HALF + (size_t)blockIdx.y * 128 * QCOLS;
    const float* Bb = keys + (size_t)hs * NKEYS * HALF + (size_t)blockIdx.x * 128 * HALF;
    float* Cb = g_scores + (size_t)hs * BSZ * NKEYS;

    __shared__ float As[2][16][128];
    __shared__ float Bs[2][16][128];

    const int tid = threadIdx.x;
    const int a_row = tid >> 2;                  // 0..127 (m for A, n for B)
    const int a_kq  = (tid & 3) * 4;

    const int cx = (tid & 15) * 8;
    const int ry = (tid >> 4) * 4;

    float acc[4][8];
    #pragma unroll
    for (int i = 0; i < 4; i++)
        #pragma unroll
        for (int j = 0; j < 8; j++) acc[i][j] = 0.f;

    float4 ra, rb;

    ra = *(const float4*)(Ab + (size_t)a_row * QCOLS + a_kq);
    rb = *(const float4*)(Bb + (size_t)a_row * HALF + a_kq);
    As[0][a_kq + 0][a_row] = ra.x; As[0][a_kq + 1][a_row] = ra.y;
    As[0][a_kq + 2][a_row] = ra.z; As[0][a_kq + 3][a_row] = ra.w;
    Bs[0][a_kq + 0][a_row] = rb.x; Bs[0][a_kq + 1][a_row] = rb.y;
    Bs[0][a_kq + 2][a_row] = rb.z; Bs[0][a_kq + 3][a_row] = rb.w;
    __syncthreads();

    const int ntiles = HALF / 16;
    for (int t = 0; t < ntiles; t++) {
        const int cur = t & 1;
        if (t + 1 < ntiles) {
            const int k0 = (t + 1) * 16;
            ra = *(const float4*)(Ab + (size_t)a_row * QCOLS + k0 + a_kq);
            rb = *(const float4*)(Bb + (size_t)a_row * HALF + k0 + a_kq);
        }

        #pragma unroll
        for (int kk = 0; kk < 16; kk++) {
            float4 av = *(float4*)&As[cur][kk][ry];
            float4 b0 = *(float4*)&Bs[cur][kk][cx];
            float4 b1 = *(float4*)&Bs[cur][kk][cx + 4];
            float a[4] = {av.x, av.y, av.z, av.w};
            float b[8] = {b0.x, b0.y, b0.z, b0.w, b1.x, b1.y, b1.z, b1.w};
            #pragma unroll
            for (int i = 0; i < 4; i++)
                #pragma unroll
                for (int j = 0; j < 8; j++) acc[i][j] += a[i] * b[j];
        }

        if (t + 1 < ntiles) {
            const int nxt = cur ^ 1;
            As[nxt][a_kq + 0][a_row] = ra.x; As[nxt][a_kq + 1][a_row] = ra.y;
            As[nxt][a_kq + 2][a_row] = ra.z; As[nxt][a_kq + 3][a_row] = ra.w;
            Bs[nxt][a_kq + 0][a_row] = rb.x; Bs[nxt][a_kq + 1][a_row] = rb.y;
            Bs[nxt][a_kq + 2][a_row] = rb.z; Bs[nxt][a_kq + 3][a_row] = rb.w;
            __syncthreads();
        }
    }

    #pragma unroll
    for (int i = 0; i < 4; i++) {
        float* Cp = Cb + (size_t)(blockIdx.y * 128 + ry + i) * NKEYS + blockIdx.x * 128 + cx;
        *(float4*)(Cp)     = make_float4(acc[i][0], acc[i][1], acc[i][2], acc[i][3]);
        *(float4*)(Cp + 4) = make_float4(acc[i][4], acc[i][5], acc[i][6], acc[i][7]);
    }
}

// ============================================================================
// Kernel 3: per-(b,h) top-k + cartesian top-k + softmax (R5 verbatim)
// ============================================================================
__global__ void __launch_bounds__(128) topk_kernel() {
    const int b    = blockIdx.x;
    const int h    = threadIdx.x >> 5;
    const int lane = threadIdx.x & 31;

    __shared__ float sv[HEADS][2][KNN];
    __shared__ int   si[HEADS][2][KNN];
    __shared__ float sbest[HEADS][KNN];
    __shared__ int   sbf[HEADS][KNN];

    #pragma unroll
    for (int s = 0; s < 2; s++) {
        const float* p = g_scores + ((size_t)(h * 2 + s)) * BSZ * NKEYS + (size_t)b * NKEYS;
        float v[16];
        #pragma unroll
        for (int j = 0; j < 16; j++) v[j] = p[j * 32 + lane];

        for (int r = 0; r < KNN; r++) {
            float bv = -1e30f; int bi = 1 << 30;
            #pragma unroll
            for (int j = 0; j < 16; j++) {
                if (v[j] > bv) { bv = v[j]; bi = j * 32 + lane; }
            }
            #pragma unroll
            for (int off = 16; off; off >>= 1) {
                float ov = __shfl_xor_sync(0xffffffffu, bv, off);
                int   oi = __shfl_xor_sync(0xffffffffu, bi, off);
                if (ov > bv || (ov == bv && oi < bi)) { bv = ov; bi = oi; }
            }
            if ((bi & 31) == lane) {
                int rem = bi >> 5;
                #pragma unroll
                for (int j = 0; j < 16; j++) if (j == rem) v[j] = -1e30f;
            }
            if (lane == 0) { sv[h][s][r] = bv; si[h][s][r] = bi; }
        }
    }
    __syncwarp();

    float cv[KNN];
    float s1l = sv[h][0][lane];
    #pragma unroll
    for (int j = 0; j < KNN; j++) cv[j] = s1l + sv[h][1][j];

    for (int r = 0; r < KNN; r++) {
        float bv = -1e30f; int bf = 1 << 30;
        #pragma unroll
        for (int j = 0; j < KNN; j++) {
            if (cv[j] > bv) { bv = cv[j]; bf = lane * 32 + j; }
        }
        #pragma unroll
        for (int off = 16; off; off >>= 1) {
            float ov = __shfl_xor_sync(0xffffffffu, bv, off);
            int   oi = __shfl_xor_sync(0xffffffffu, bf, off);
            if (ov > bv || (ov == bv && oi < bf)) { bv = ov; bf = oi; }
        }
        if ((bf >> 5) == lane) {
            int rem = bf & 31;
            #pragma unroll
            for (int j = 0; j < KNN; j++) if (j == rem) cv[j] = -1e30f;
        }
        if (lane == 0) { sbest[h][r] = bv; sbf[h][r] = bf; }
    }
    __syncwarp();

    float m = sbest[h][0];
    float e = expf(sbest[h][lane] - m);
    float sum = e;
    #pragma unroll
    for (int off = 16; off; off >>= 1) sum += __shfl_xor_sync(0xffffffffu, sum, off);
    float wgt = e / sum;

    int f = sbf[h][lane];
    int index = si[h][0][f >> 5] * NKEYS + si[h][1][f & 31];

    g_w  [(size_t)(b * HEADS + h) * KNN + lane] = wgt;
    g_idx[(size_t)(b * HEADS + h) * KNN + lane] = index;
}

// ============================================================================
// Kernel 4: gather + weighted sum (R5 verbatim: regs=32, occ 92%, 88% DRAM)
// ============================================================================
__global__ void __launch_bounds__(256) gather_kernel(const float* __restrict__ values,
                                                     float* __restrict__ out) {
    const int b = blockIdx.x;
    const int t = threadIdx.x;
    __shared__ float ws[HEADS * KNN];
    __shared__ int   is[HEADS * KNN];
    if (t < HEADS * KNN) {
        ws[t] = g_w[(size_t)b * HEADS * KNN + t];
        is[t] = g_idx[(size_t)b * HEADS * KNN + t];
    }
    __syncthreads();

    const float4* V = (const float4*)values;
    float4 acc = make_float4(0.f, 0.f, 0.f, 0.f);

    #pragma unroll 8
    for (int k = 0; k < HEADS * KNN; k++) {
        float w = ws[k];
        size_t row = (size_t)is[k];
        float4 v = V[row * (VDIM / 4) + t];
        acc.x += w * v.x; acc.y += w * v.y;
        acc.z += w * v.z; acc.w += w * v.w;
    }
    ((float4*)out)[(size_t)b * (VDIM / 4) + t] = acc;
}

// ============================================================================
extern "C" void kernel_launch(void* const* d_in, const int* in_sizes, int n_in,
                              void* d_out, int out_size) {
    const float* x      = (const float*)d_in[0];   // (4096, 1024)
    const float* wq     = (const float*)d_in[1];   // (1024, 2048)
    const float* keys   = (const float*)d_in[2];   // (4, 2, 512, 256)
    const float* values = (const float*)d_in[3];   // (262144, 1024)
    float* out = (float*)d_out;                    // (4096, 1024)

    {
        dim3 grid(QCOLS / 128, BSZ / 128);  // (16, 32)
        q_gemm<<<grid, 512>>>(x, wq);
    }
    {
        dim3 grid(NKEYS / 128, BSZ / 128, 8);  // (4, 32, 8)
        score_gemm<<<grid, 512>>>(keys);
    }
    topk_kernel<<<BSZ, 128>>>();
    gather_kernel<<<BSZ, 256>>>(values, out);
}

// round 14
// speedup vs baseline: 1.4574x; 1.4574x over previous
#include <cuda_runtime.h>
#include <cstdint>

#define BSZ    4096
#define HEADS  4
#define HALF   256
#define NKEYS  512
#define KNN    32
#define VDIM   1024
#define INDIM  1024
#define QCOLS  2048      // HEADS * K_DIM = 4*512

// ---- scratch (device globals: allocation-free) ----
__device__ float g_q[(size_t)BSZ * QCOLS];               // 32 MB
__device__ float g_scores[(size_t)8 * BSZ * NKEYS];      // 64 MB : [hs][b][n]
__device__ float g_w[(size_t)BSZ * HEADS * KNN];         // 2 MB
__device__ int   g_idx[(size_t)BSZ * HEADS * KNN];       // 2 MB

// ============================================================================
// Kernel 1: q = x @ Wq   (M=4096, N=2048, K=1024)  NN, fp32.
//   256 threads, CTA tile 128(M) x 64(N), ktile 16, per-thread 8x4 (32 accs).
//   3 CTAs/SM (24 warps) for latency hiding; regs budget 84.
//   Per-element accumulation strictly k-sequential -> bit-identical to R5.
// ============================================================================
__global__ void __launch_bounds__(256, 3) q_gemm(const float* __restrict__ A,
                                                 const float* __restrict__ B) {
    const int N = QCOLS;
    const int K = INDIM;
    __shared__ float As[2][16][128];
    __shared__ float Bs[2][16][64];

    const int tid = threadIdx.x;
    const float* Ab = A + (size_t)blockIdx.y * 128 * INDIM;
    const float* Bb = B + blockIdx.x * 64;

    // A loads: 2 float4/thread (rows tid>>2 and +64, k quad (tid&3)*4)
    const int a_row0 = tid >> 2;                 // 0..63
    const int a_row1 = a_row0 + 64;
    const int a_kq   = (tid & 3) * 4;            // 0,4,8,12
    // B loads: 1 float4/thread (k row tid>>4, col quad (tid&15)*4)
    const int b_kr   = tid >> 4;                 // 0..15
    const int b_cq   = (tid & 15) * 4;           // 0..60

    // compute mapping: 8 rows x 4 cols per thread
    const int cx = (tid & 15) * 4;               // col base 0..60
    const int ry = (tid >> 4) * 8;               // row base 0..120

    float acc[8][4];
    #pragma unroll
    for (int i = 0; i < 8; i++)
        #pragma unroll
        for (int j = 0; j < 4; j++) acc[i][j] = 0.f;

    float4 ra0, ra1, rb;

    // prologue: tile 0
    ra0 = *(const float4*)(Ab + (size_t)a_row0 * INDIM + a_kq);
    ra1 = *(const float4*)(Ab + (size_t)a_row1 * INDIM + a_kq);
    rb  = *(const float4*)(Bb + (size_t)b_kr * N + b_cq);
    As[0][a_kq + 0][a_row0] = ra0.x; As[0][a_kq + 1][a_row0] = ra0.y;
    As[0][a_kq + 2][a_row0] = ra0.z; As[0][a_kq + 3][a_row0] = ra0.w;
    As[0][a_kq + 0][a_row1] = ra1.x; As[0][a_kq + 1][a_row1] = ra1.y;
    As[0][a_kq + 2][a_row1] = ra1.z; As[0][a_kq + 3][a_row1] = ra1.w;
    *(float4*)&Bs[0][b_kr][b_cq] = rb;
    __syncthreads();

    const int ntiles = K / 16;
    for (int t = 0; t < ntiles; t++) {
        const int cur = t & 1;
        if (t + 1 < ntiles) {
            const int k0 = (t + 1) * 16;
            ra0 = *(const float4*)(Ab + (size_t)a_row0 * INDIM + k0 + a_kq);
            ra1 = *(const float4*)(Ab + (size_t)a_row1 * INDIM + k0 + a_kq);
            rb  = *(const float4*)(Bb + (size_t)(k0 + b_kr) * N + b_cq);
        }

        #pragma unroll
        for (int kk = 0; kk < 16; kk++) {
            float4 a0 = *(float4*)&As[cur][kk][ry];
            float4 a1 = *(float4*)&As[cur][kk][ry + 4];
            float4 bv = *(float4*)&Bs[cur][kk][cx];
            float a[8] = {a0.x, a0.y, a0.z, a0.w, a1.x, a1.y, a1.z, a1.w};
            float b[4] = {bv.x, bv.y, bv.z, bv.w};
            #pragma unroll
            for (int i = 0; i < 8; i++)
                #pragma unroll
                for (int j = 0; j < 4; j++) acc[i][j] += a[i] * b[j];
        }

        if (t + 1 < ntiles) {
            const int nxt = cur ^ 1;
            As[nxt][a_kq + 0][a_row0] = ra0.x; As[nxt][a_kq + 1][a_row0] = ra0.y;
            As[nxt][a_kq + 2][a_row0] = ra0.z; As[nxt][a_kq + 3][a_row0] = ra0.w;
            As[nxt][a_kq + 0][a_row1] = ra1.x; As[nxt][a_kq + 1][a_row1] = ra1.y;
            As[nxt][a_kq + 2][a_row1] = ra1.z; As[nxt][a_kq + 3][a_row1] = ra1.w;
            *(float4*)&Bs[nxt][b_kr][b_cq] = rb;
            __syncthreads();
        }
    }

    #pragma unroll
    for (int i = 0; i < 8; i++) {
        float* Cp = g_q + (size_t)(blockIdx.y * 128 + ry + i) * N + blockIdx.x * 64 + cx;
        *(float4*)(Cp) = make_float4(acc[i][0], acc[i][1], acc[i][2], acc[i][3]);
    }
}

// ============================================================================
// Kernel 2: scores[hs][b][n] = sum_d q[b, hs*256+d] * keys[hs][n][d]  (NT)
//   per hs: M=4096, N=512, K=256. grid=(8, 32, 8). Same 128x64 / 8x4 scheme.
// ============================================================================
__global__ void __launch_bounds__(256, 3) score_gemm(const float* __restrict__ keys) {
    const int hs = blockIdx.z;
    const float* Ab = g_q + hs * HALF + (size_t)blockIdx.y * 128 * QCOLS;
    const float* Bb = keys + (size_t)hs * NKEYS * HALF + (size_t)blockIdx.x * 64 * HALF;
    float* Cb = g_scores + (size_t)hs * BSZ * NKEYS;

    __shared__ float As[2][16][128];
    __shared__ float Bs[2][16][64];

    const int tid = threadIdx.x;
    const int a_row0 = tid >> 2;                 // 0..63
    const int a_row1 = a_row0 + 64;
    const int a_kq   = (tid & 3) * 4;
    const int b_nrow = tid >> 2;                 // 0..63 (keys n row)

    const int cx = (tid & 15) * 4;
    const int ry = (tid >> 4) * 8;

    float acc[8][4];
    #pragma unroll
    for (int i = 0; i < 8; i++)
        #pragma unroll
        for (int j = 0; j < 4; j++) acc[i][j] = 0.f;

    float4 ra0, ra1, rb;

    ra0 = *(const float4*)(Ab + (size_t)a_row0 * QCOLS + a_kq);
    ra1 = *(const float4*)(Ab + (size_t)a_row1 * QCOLS + a_kq);
    rb  = *(const float4*)(Bb + (size_t)b_nrow * HALF + a_kq);
    As[0][a_kq + 0][a_row0] = ra0.x; As[0][a_kq + 1][a_row0] = ra0.y;
    As[0][a_kq + 2][a_row0] = ra0.z; As[0][a_kq + 3][a_row0] = ra0.w;
    As[0][a_kq + 0][a_row1] = ra1.x; As[0][a_kq + 1][a_row1] = ra1.y;
    As[0][a_kq + 2][a_row1] = ra1.z; As[0][a_kq + 3][a_row1] = ra1.w;
    Bs[0][a_kq + 0][b_nrow] = rb.x; Bs[0][a_kq + 1][b_nrow] = rb.y;
    Bs[0][a_kq + 2][b_nrow] = rb.z; Bs[0][a_kq + 3][b_nrow] = rb.w;
    __syncthreads();

    const int ntiles = HALF / 16;
    for (int t = 0; t < ntiles; t++) {
        const int cur = t & 1;
        if (t + 1 < ntiles) {
            const int k0 = (t + 1) * 16;
            ra0 = *(const float4*)(Ab + (size_t)a_row0 * QCOLS + k0 + a_kq);
            ra1 = *(const float4*)(Ab + (size_t)a_row1 * QCOLS + k0 + a_kq);
            rb  = *(const float4*)(Bb + (size_t)b_nrow * HALF + k0 + a_kq);
        }

        #pragma unroll
        for (int kk = 0; kk < 16; kk++) {
            float4 a0 = *(float4*)&As[cur][kk][ry];
            float4 a1 = *(float4*)&As[cur][kk][ry + 4];
            float4 bv = *(float4*)&Bs[cur][kk][cx];
            float a[8] = {a0.x, a0.y, a0.z, a0.w, a1.x, a1.y, a1.z, a1.w};
            float b[4] = {bv.x, bv.y, bv.z, bv.w};
            #pragma unroll
            for (int i = 0; i < 8; i++)
                #pragma unroll
                for (int j = 0; j < 4; j++) acc[i][j] += a[i] * b[j];
        }

        if (t + 1 < ntiles) {
            const int nxt = cur ^ 1;
            As[nxt][a_kq + 0][a_row0] = ra0.x; As[nxt][a_kq + 1][a_row0] = ra0.y;
            As[nxt][a_kq + 2][a_row0] = ra0.z; As[nxt][a_kq + 3][a_row0] = ra0.w;
            As[nxt][a_kq + 0][a_row1] = ra1.x; As[nxt][a_kq + 1][a_row1] = ra1.y;
            As[nxt][a_kq + 2][a_row1] = ra1.z; As[nxt][a_kq + 3][a_row1] = ra1.w;
            Bs[nxt][a_kq + 0][b_nrow] = rb.x; Bs[nxt][a_kq + 1][b_nrow] = rb.y;
            Bs[nxt][a_kq + 2][b_nrow] = rb.z; Bs[nxt][a_kq + 3][b_nrow] = rb.w;
            __syncthreads();
        }
    }

    #pragma unroll
    for (int i = 0; i < 8; i++) {
        float* Cp = Cb + (size_t)(blockIdx.y * 128 + ry + i) * NKEYS + blockIdx.x * 64 + cx;
        *(float4*)(Cp) = make_float4(acc[i][0], acc[i][1], acc[i][2], acc[i][3]);
    }
}

// ============================================================================
// Kernel 3: per-(b,h) top-k + cartesian top-k + softmax (R5 verbatim)
// ============================================================================
__global__ void __launch_bounds__(128) topk_kernel() {
    const int b    = blockIdx.x;
    const int h    = threadIdx.x >> 5;
    const int lane = threadIdx.x & 31;

    __shared__ float sv[HEADS][2][KNN];
    __shared__ int   si[HEADS][2][KNN];
    __shared__ float sbest[HEADS][KNN];
    __shared__ int   sbf[HEADS][KNN];

    #pragma unroll
    for (int s = 0; s < 2; s++) {
        const float* p = g_scores + ((size_t)(h * 2 + s)) * BSZ * NKEYS + (size_t)b * NKEYS;
        float v[16];
        #pragma unroll
        for (int j = 0; j < 16; j++) v[j] = p[j * 32 + lane];

        for (int r = 0; r < KNN; r++) {
            float bv = -1e30f; int bi = 1 << 30;
            #pragma unroll
            for (int j = 0; j < 16; j++) {
                if (v[j] > bv) { bv = v[j]; bi = j * 32 + lane; }
            }
            #pragma unroll
            for (int off = 16; off; off >>= 1) {
                float ov = __shfl_xor_sync(0xffffffffu, bv, off);
                int   oi = __shfl_xor_sync(0xffffffffu, bi, off);
                if (ov > bv || (ov == bv && oi < bi)) { bv = ov; bi = oi; }
            }
            if ((bi & 31) == lane) {
                int rem = bi >> 5;
                #pragma unroll
                for (int j = 0; j < 16; j++) if (j == rem) v[j] = -1e30f;
            }
            if (lane == 0) { sv[h][s][r] = bv; si[h][s][r] = bi; }
        }
    }
    __syncwarp();

    float cv[KNN];
    float s1l = sv[h][0][lane];
    #pragma unroll
    for (int j = 0; j < KNN; j++) cv[j] = s1l + sv[h][1][j];

    for (int r = 0; r < KNN; r++) {
        float bv = -1e30f; int bf = 1 << 30;
        #pragma unroll
        for (int j = 0; j < KNN; j++) {
            if (cv[j] > bv) { bv = cv[j]; bf = lane * 32 + j; }
        }
        #pragma unroll
        for (int off = 16; off; off >>= 1) {
            float ov = __shfl_xor_sync(0xffffffffu, bv, off);
            int   oi = __shfl_xor_sync(0xffffffffu, bf, off);
            if (ov > bv || (ov == bv && oi < bf)) { bv = ov; bf = oi; }
        }
        if ((bf >> 5) == lane) {
            int rem = bf & 31;
            #pragma unroll
            for (int j = 0; j < KNN; j++) if (j == rem) cv[j] = -1e30f;
        }
        if (lane == 0) { sbest[h][r] = bv; sbf[h][r] = bf; }
    }
    __syncwarp();

    float m = sbest[h][0];
    float e = expf(sbest[h][lane] - m);
    float sum = e;
    #pragma unroll
    for (int off = 16; off; off >>= 1) sum += __shfl_xor_sync(0xffffffffu, sum, off);
    float wgt = e / sum;

    int f = sbf[h][lane];
    int index = si[h][0][f >> 5] * NKEYS + si[h][1][f & 31];

    g_w  [(size_t)(b * HEADS + h) * KNN + lane] = wgt;
    g_idx[(size_t)(b * HEADS + h) * KNN + lane] = index;
}

// ============================================================================
// Kernel 4: gather + weighted sum (R5 verbatim: regs=32, occ 92%, 88% DRAM)
// ============================================================================
__global__ void __launch_bounds__(256) gather_kernel(const float* __restrict__ values,
                                                     float* __restrict__ out) {
    const int b = blockIdx.x;
    const int t = threadIdx.x;
    __shared__ float ws[HEADS * KNN];
    __shared__ int   is[HEADS * KNN];
    if (t < HEADS * KNN) {
        ws[t] = g_w[(size_t)b * HEADS * KNN + t];
        is[t] = g_idx[(size_t)b * HEADS * KNN + t];
    }
    __syncthreads();

    const float4* V = (const float4*)values;
    float4 acc = make_float4(0.f, 0.f, 0.f, 0.f);

    #pragma unroll 8
    for (int k = 0; k < HEADS * KNN; k++) {
        float w = ws[k];
        size_t row = (size_t)is[k];
        float4 v = V[row * (VDIM / 4) + t];
        acc.x += w * v.x; acc.y += w * v.y;
        acc.z += w * v.z; acc.w += w * v.w;
    }
    ((float4*)out)[(size_t)b * (VDIM / 4) + t] = acc;
}

// ============================================================================
extern "C" void kernel_launch(void* const* d_in, const int* in_sizes, int n_in,
                              void* d_out, int out_size) {
    const float* x      = (const float*)d_in[0];   // (4096, 1024)
    const float* wq     = (const float*)d_in[1];   // (1024, 2048)
    const float* keys   = (const float*)d_in[2];   // (4, 2, 512, 256)
    const float* values = (const float*)d_in[3];   // (262144, 1024)
    float* out = (float*)d_out;                    // (4096, 1024)

    {
        dim3 grid(QCOLS / 64, BSZ / 128);   // (32, 32)
        q_gemm<<<grid, 256>>>(x, wq);
    }
    {
        dim3 grid(NKEYS / 64, BSZ / 128, 8);  // (8, 32, 8)
        score_gemm<<<grid, 256>>>(keys);
    }
    topk_kernel<<<BSZ, 128>>>();
    gather_kernel<<<BSZ, 256>>>(values, out);
}

// round 16
// speedup vs baseline: 2.1335x; 1.4639x over previous
#include <cuda_runtime.h>
#include <cstdint>

#define BSZ    4096
#define HEADS  4
#define HALF   256
#define NKEYS  512
#define KNN    32
#define VDIM   1024
#define INDIM  1024
#define QCOLS  2048      // HEADS * K_DIM = 4*512

#define KT     32        // q_gemm k-tile
#define QSMEM  (2 * KT * 128 * 2 * (int)sizeof(float))   // 65536 B

// ---- scratch (device globals: allocation-free) ----
__device__ float g_q[(size_t)BSZ * QCOLS];               // 32 MB
__device__ float g_scores[(size_t)8 * BSZ * NKEYS];      // 64 MB : [hs][b][n]
__device__ float g_w[(size_t)BSZ * HEADS * KNN];         // 2 MB
__device__ int   g_idx[(size_t)BSZ * HEADS * KNN];       // 2 MB

// ---- cp.async helpers (Ampere+ LDGSTS; legal on sm_103) ----
__device__ __forceinline__ void cp16(float* smem_dst, const float* gsrc) {
    uint32_t s = (uint32_t)__cvta_generic_to_shared(smem_dst);
    asm volatile("cp.async.cg.shared.global [%0], [%1], 16;" :: "r"(s), "l"(gsrc) : "memory");
}
#define CP_COMMIT() asm volatile("cp.async.commit_group;" ::: "memory")
#define CP_WAIT0()  asm volatile("cp.async.wait_group 0;" ::: "memory")

// ============================================================================
// Kernel 1: q = x @ Wq   (M=4096, N=2048, K=1024)  NN, fp32.
//   256 thr, CTA tile 128x128, ktile 32 (half the barriers of R5), 8x8/thread.
//   B tile: cp.async gmem->smem (no reg staging). A tile: LDG->reg->STS
//   transpose (16 staging regs, same as R5). Per-element accumulation
//   strictly k-ascending -> bit-identical to the proven R5 kernel.
// ============================================================================
__global__ void __launch_bounds__(256, 2) q_gemm(const float* __restrict__ A,
                                                 const float* __restrict__ B) {
    extern __shared__ float smem[];
    float* AsB = smem;                       // [2][KT][128], A transposed [k][row]
    float* BsB = smem + 2 * KT * 128;        // [2][KT][128], B [k][col]
#define AS(buf, k, r) AsB[(((buf) * KT + (k)) << 7) + (r)]
#define BS(buf, k, c) BsB[(((buf) * KT + (k)) << 7) + (c)]

    const int N = QCOLS;
    const int tid = threadIdx.x;
    const float* Ab = A + (size_t)blockIdx.y * 128 * INDIM;
    const float* Bb = B + blockIdx.x * 128;

    const int tx = (tid & 15) * 8;
    const int ty = (tid >> 4) * 8;

    float acc[8][8];
    #pragma unroll
    for (int i = 0; i < 8; i++)
        #pragma unroll
        for (int j = 0; j < 8; j++) acc[i][j] = 0.f;

    float4 ra[2];            // A staging: 2 float4 per half (issued in 2 waves of 2)

    // ---- prologue: tile 0 ----
    #pragma unroll
    for (int i = 0; i < 4; i++) {            // B tile: 4 cp.async per thread
        int idx = tid + i * 256;
        int kr  = idx >> 5;                  // 0..31
        int cq  = (idx & 31) * 4;            // 0..124
        cp16(&BS(0, kr, cq), Bb + (size_t)kr * N + cq);
    }
    CP_COMMIT();
    #pragma unroll
    for (int half = 0; half < 2; half++) {   // A tile: 4 float4, 2 waves
        #pragma unroll
        for (int i = 0; i < 2; i++) {
            int idx = tid + (half * 2 + i) * 256;
            int row = idx >> 3;              // 0..127
            int kq  = (idx & 7) * 4;         // 0..28
            ra[i] = *(const float4*)(Ab + (size_t)row * INDIM + kq);
        }
        #pragma unroll
        for (int i = 0; i < 2; i++) {
            int idx = tid + (half * 2 + i) * 256;
            int row = idx >> 3;
            int kq  = (idx & 7) * 4;
            AS(0, kq + 0, row) = ra[i].x; AS(0, kq + 1, row) = ra[i].y;
            AS(0, kq + 2, row) = ra[i].z; AS(0, kq + 3, row) = ra[i].w;
        }
    }
    CP_WAIT0();
    __syncthreads();

    const int ntiles = INDIM / KT;           // 32
    float4 rpre[4];                          // A prefetch staging (16 regs)

    for (int t = 0; t < ntiles; t++) {
        const int cur = t & 1;
        const int nxt = cur ^ 1;
        if (t + 1 < ntiles) {
            const int k0 = (t + 1) * KT;
            #pragma unroll
            for (int i = 0; i < 4; i++) {    // B(t+1) via cp.async -> overlaps compute
                int idx = tid + i * 256;
                int kr  = idx >> 5;
                int cq  = (idx & 31) * 4;
                cp16(&BS(nxt, kr, cq), Bb + (size_t)(k0 + kr) * N + cq);
            }
            CP_COMMIT();
            #pragma unroll
            for (int i = 0; i < 4; i++) {    // A(t+1) into regs -> overlaps compute
                int idx = tid + i * 256;
                int row = idx >> 3;
                int kq  = (idx & 7) * 4;
                rpre[i] = *(const float4*)(Ab + (size_t)row * INDIM + k0 + kq);
            }
        }

        #pragma unroll
        for (int kk = 0; kk < KT; kk++) {
            float a[8], b[8];
            *(float4*)(a)     = *(float4*)&AS(cur, kk, ty);
            *(float4*)(a + 4) = *(float4*)&AS(cur, kk, ty + 4);
            *(float4*)(b)     = *(float4*)&BS(cur, kk, tx);
            *(float4*)(b + 4) = *(float4*)&BS(cur, kk, tx + 4);
            #pragma unroll
            for (int i = 0; i < 8; i++)
                #pragma unroll
                for (int j = 0; j < 8; j++) acc[i][j] += a[i] * b[j];
        }

        if (t + 1 < ntiles) {
            #pragma unroll
            for (int i = 0; i < 4; i++) {
                int idx = tid + i * 256;
                int row = idx >> 3;
                int kq  = (idx & 7) * 4;
                AS(nxt, kq + 0, row) = rpre[i].x; AS(nxt, kq + 1, row) = rpre[i].y;
                AS(nxt, kq + 2, row) = rpre[i].z; AS(nxt, kq + 3, row) = rpre[i].w;
            }
            CP_WAIT0();
            __syncthreads();
        }
    }

    #pragma unroll
    for (int i = 0; i < 8; i++) {
        float* Cp = g_q + (size_t)(blockIdx.y * 128 + ty + i) * N + blockIdx.x * 128 + tx;
        *(float4*)(Cp)     = make_float4(acc[i][0], acc[i][1], acc[i][2], acc[i][3]);
        *(float4*)(Cp + 4) = make_float4(acc[i][4], acc[i][5], acc[i][6], acc[i][7]);
    }
#undef AS
#undef BS
}

// ============================================================================
// Kernel 2: scores[hs][b][n] = sum_d q[b, hs*256+d] * keys[hs][n][d]  (NT)
//   per hs: M=4096, N=512, K=256. grid=(4,32,8). R5 verbatim (proven).
// ============================================================================
__global__ void __launch_bounds__(256, 2) score_gemm(const float* __restrict__ keys) {
    const int hs = blockIdx.z;
    const float* Ab = g_q + hs * HALF + (size_t)blockIdx.y * 128 * QCOLS;
    const float* Bb = keys + (size_t)hs * NKEYS * HALF + (size_t)blockIdx.x * 128 * HALF;
    float* Cb = g_scores + (size_t)hs * BSZ * NKEYS;

    __shared__ float As[2][16][128];
    __shared__ float Bs[2][16][128];

    const int tid = threadIdx.x;
    const int a_row0 = tid >> 2;
    const int a_row1 = a_row0 + 64;
    const int a_kq   = (tid & 3) * 4;

    float acc[8][8];
    #pragma unroll
    for (int i = 0; i < 8; i++)
        #pragma unroll
        for (int j = 0; j < 8; j++) acc[i][j] = 0.f;

    const int tx = (tid & 15) * 8;
    const int ty = (tid >> 4) * 8;

    float4 ra0, ra1, rb0, rb1;

    ra0 = *(const float4*)(Ab + (size_t)a_row0 * QCOLS + a_kq);
    ra1 = *(const float4*)(Ab + (size_t)a_row1 * QCOLS + a_kq);
    rb0 = *(const float4*)(Bb + (size_t)a_row0 * HALF + a_kq);
    rb1 = *(const float4*)(Bb + (size_t)a_row1 * HALF + a_kq);
    As[0][a_kq + 0][a_row0] = ra0.x; As[0][a_kq + 1][a_row0] = ra0.y;
    As[0][a_kq + 2][a_row0] = ra0.z; As[0][a_kq + 3][a_row0] = ra0.w;
    As[0][a_kq + 0][a_row1] = ra1.x; As[0][a_kq + 1][a_row1] = ra1.y;
    As[0][a_kq + 2][a_row1] = ra1.z; As[0][a_kq + 3][a_row1] = ra1.w;
    Bs[0][a_kq + 0][a_row0] = rb0.x; Bs[0][a_kq + 1][a_row0] = rb0.y;
    Bs[0][a_kq + 2][a_row0] = rb0.z; Bs[0][a_kq + 3][a_row0] = rb0.w;
    Bs[0][a_kq + 0][a_row1] = rb1.x; Bs[0][a_kq + 1][a_row1] = rb1.y;
    Bs[0][a_kq + 2][a_row1] = rb1.z; Bs[0][a_kq + 3][a_row1] = rb1.w;
    __syncthreads();

    const int ntiles = HALF / 16;
    for (int t = 0; t < ntiles; t++) {
        const int cur = t & 1;
        if (t + 1 < ntiles) {
            const int k0 = (t + 1) * 16;
            ra0 = *(const float4*)(Ab + (size_t)a_row0 * QCOLS + k0 + a_kq);
            ra1 = *(const float4*)(Ab + (size_t)a_row1 * QCOLS + k0 + a_kq);
            rb0 = *(const float4*)(Bb + (size_t)a_row0 * HALF + k0 + a_kq);
            rb1 = *(const float4*)(Bb + (size_t)a_row1 * HALF + k0 + a_kq);
        }

        #pragma unroll
        for (int kk = 0; kk < 16; kk++) {
            float a[8], b[8];
            *(float4*)(a)     = *(float4*)&As[cur][kk][ty];
            *(float4*)(a + 4) = *(float4*)&As[cur][kk][ty + 4];
            *(float4*)(b)     = *(float4*)&Bs[cur][kk][tx];
            *(float4*)(b + 4) = *(float4*)&Bs[cur][kk][tx + 4];
            #pragma unroll
            for (int i = 0; i < 8; i++)
                #pragma unroll
                for (int j = 0; j < 8; j++) acc[i][j] += a[i] * b[j];
        }

        if (t + 1 < ntiles) {
            const int nxt = cur ^ 1;
            As[nxt][a_kq + 0][a_row0] = ra0.x; As[nxt][a_kq + 1][a_row0] = ra0.y;
            As[nxt][a_kq + 2][a_row0] = ra0.z; As[nxt][a_kq + 3][a_row0] = ra0.w;
            As[nxt][a_kq + 0][a_row1] = ra1.x; As[nxt][a_kq + 1][a_row1] = ra1.y;
            As[nxt][a_kq + 2][a_row1] = ra1.z; As[nxt][a_kq + 3][a_row1] = ra1.w;
            Bs[nxt][a_kq + 0][a_row0] = rb0.x; Bs[nxt][a_kq + 1][a_row0] = rb0.y;
            Bs[nxt][a_kq + 2][a_row0] = rb0.z; Bs[nxt][a_kq + 3][a_row0] = rb0.w;
            Bs[nxt][a_kq + 0][a_row1] = rb1.x; Bs[nxt][a_kq + 1][a_row1] = rb1.y;
            Bs[nxt][a_kq + 2][a_row1] = rb1.z; Bs[nxt][a_kq + 3][a_row1] = rb1.w;
            __syncthreads();
        }
    }

    #pragma unroll
    for (int i = 0; i < 8; i++) {
        float* Cp = Cb + (size_t)(blockIdx.y * 128 + ty + i) * NKEYS + blockIdx.x * 128 + tx;
        *(float4*)(Cp)     = make_float4(acc[i][0], acc[i][1], acc[i][2], acc[i][3]);
        *(float4*)(Cp + 4) = make_float4(acc[i][4], acc[i][5], acc[i][6], acc[i][7]);
    }
}

// ============================================================================
// Kernel 3: per-(b,h) top-k + cartesian top-k + softmax (R5 verbatim)
// ============================================================================
__global__ void __launch_bounds__(128) topk_kernel() {
    const int b    = blockIdx.x;
    const int h    = threadIdx.x >> 5;
    const int lane = threadIdx.x & 31;

    __shared__ float sv[HEADS][2][KNN];
    __shared__ int   si[HEADS][2][KNN];
    __shared__ float sbest[HEADS][KNN];
    __shared__ int   sbf[HEADS][KNN];

    #pragma unroll
    for (int s = 0; s < 2; s++) {
        const float* p = g_scores + ((size_t)(h * 2 + s)) * BSZ * NKEYS + (size_t)b * NKEYS;
        float v[16];
        #pragma unroll
        for (int j = 0; j < 16; j++) v[j] = p[j * 32 + lane];

        for (int r = 0; r < KNN; r++) {
            float bv = -1e30f; int bi = 1 << 30;
            #pragma unroll
            for (int j = 0; j < 16; j++) {
                if (v[j] > bv) { bv = v[j]; bi = j * 32 + lane; }
            }
            #pragma unroll
            for (int off = 16; off; off >>= 1) {
                float ov = __shfl_xor_sync(0xffffffffu, bv, off);
                int   oi = __shfl_xor_sync(0xffffffffu, bi, off);
                if (ov > bv || (ov == bv && oi < bi)) { bv = ov; bi = oi; }
            }
            if ((bi & 31) == lane) {
                int rem = bi >> 5;
                #pragma unroll
                for (int j = 0; j < 16; j++) if (j == rem) v[j] = -1e30f;
            }
            if (lane == 0) { sv[h][s][r] = bv; si[h][s][r] = bi; }
        }
    }
    __syncwarp();

    float cv[KNN];
    float s1l = sv[h][0][lane];
    #pragma unroll
    for (int j = 0; j < KNN; j++) cv[j] = s1l + sv[h][1][j];

    for (int r = 0; r < KNN; r++) {
        float bv = -1e30f; int bf = 1 << 30;
        #pragma unroll
        for (int j = 0; j < KNN; j++) {
            if (cv[j] > bv) { bv = cv[j]; bf = lane * 32 + j; }
        }
        #pragma unroll
        for (int off = 16; off; off >>= 1) {
            float ov = __shfl_xor_sync(0xffffffffu, bv, off);
            int   oi = __shfl_xor_sync(0xffffffffu, bf, off);
            if (ov > bv || (ov == bv && oi < bf)) { bv = ov; bf = oi; }
        }
        if ((bf >> 5) == lane) {
            int rem = bf & 31;
            #pragma unroll
            for (int j = 0; j < KNN; j++) if (j == rem) cv[j] = -1e30f;
        }
        if (lane == 0) { sbest[h][r] = bv; sbf[h][r] = bf; }
    }
    __syncwarp();

    float m = sbest[h][0];
    float e = expf(sbest[h][lane] - m);
    float sum = e;
    #pragma unroll
    for (int off = 16; off; off >>= 1) sum += __shfl_xor_sync(0xffffffffu, sum, off);
    float wgt = e / sum;

    int f = sbf[h][lane];
    int index = si[h][0][f >> 5] * NKEYS + si[h][1][f & 31];

    g_w  [(size_t)(b * HEADS + h) * KNN + lane] = wgt;
    g_idx[(size_t)(b * HEADS + h) * KNN + lane] = index;
}

// ============================================================================
// Kernel 4: gather + weighted sum (R5 verbatim: regs=32, occ 92%, 88% DRAM)
// ============================================================================
__global__ void __launch_bounds__(256) gather_kernel(const float* __restrict__ values,
                                                     float* __restrict__ out) {
    const int b = blockIdx.x;
    const int t = threadIdx.x;
    __shared__ float ws[HEADS * KNN];
    __shared__ int   is[HEADS * KNN];
    if (t < HEADS * KNN) {
        ws[t] = g_w[(size_t)b * HEADS * KNN + t];
        is[t] = g_idx[(size_t)b * HEADS * KNN + t];
    }
    __syncthreads();

    const float4* V = (const float4*)values;
    float4 acc = make_float4(0.f, 0.f, 0.f, 0.f);

    #pragma unroll 8
    for (int k = 0; k < HEADS * KNN; k++) {
        float w = ws[k];
        size_t row = (size_t)is[k];
        float4 v = V[row * (VDIM / 4) + t];
        acc.x += w * v.x; acc.y += w * v.y;
        acc.z += w * v.z; acc.w += w * v.w;
    }
    ((float4*)out)[(size_t)b * (VDIM / 4) + t] = acc;
}

// ============================================================================
extern "C" void kernel_launch(void* const* d_in, const int* in_sizes, int n_in,
                              void* d_out, int out_size) {
    const float* x      = (const float*)d_in[0];   // (4096, 1024)
    const float* wq     = (const float*)d_in[1];   // (1024, 2048)
    const float* keys   = (const float*)d_in[2];   // (4, 2, 512, 256)
    const float* values = (const float*)d_in[3];   // (262144, 1024)
    float* out = (float*)d_out;                    // (4096, 1024)

    cudaFuncSetAttribute(q_gemm, cudaFuncAttributeMaxDynamicSharedMemorySize, QSMEM);

    {
        dim3 grid(QCOLS / 128, BSZ / 128);  // (16, 32)
        q_gemm<<<grid, 256, QSMEM>>>(x, wq);
    }
    {
        dim3 grid(NKEYS / 128, BSZ / 128, 8);  // (4, 32, 8)
        score_gemm<<<grid, 256>>>(keys);
    }
    topk_kernel<<<BSZ, 128>>>();
    gather_kernel<<<BSZ, 256>>>(values, out);
}

// round 17
// speedup vs baseline: 2.2769x; 1.0672x over previous
#include <cuda_runtime.h>
#include <cstdint>

#define BSZ    4096
#define HEADS  4
#define HALF   256
#define NKEYS  512
#define KNN    32
#define VDIM   1024
#define INDIM  1024
#define QCOLS  2048      // HEADS * K_DIM = 4*512

// ---- scratch (device globals: allocation-free) ----
__device__ float g_q[(size_t)BSZ * QCOLS];               // 32 MB
__device__ float g_scores[(size_t)8 * BSZ * NKEYS];      // 64 MB : [hs][b][n]
__device__ float g_w[(size_t)BSZ * HEADS * KNN];         // 2 MB
__device__ int   g_idx[(size_t)BSZ * HEADS * KNN];       // 2 MB

// ============================================================================
// Kernel 1: q = x @ Wq   (M=4096, N=2048, K=1024)  NN, fp32, 128x128x16 tiles
//   R5 double-buffered kernel; B-fragment loads split 4+4 (conflict-free LDS).
//   Per-element accumulation order identical to R5 -> bit-identical output.
// ============================================================================
__global__ void __launch_bounds__(256, 2) q_gemm(const float* __restrict__ A,
                                                 const float* __restrict__ B) {
    const int N = QCOLS;
    const int K = INDIM;
    __shared__ float As[2][16][128];
    __shared__ float Bs[2][16][128];

    const int tid = threadIdx.x;
    const float* Ab = A + (size_t)blockIdx.y * 128 * INDIM;
    const float* Bb = B + blockIdx.x * 128;

    const int a_row0 = tid >> 2;                 // 0..63
    const int a_row1 = a_row0 + 64;
    const int a_kq   = (tid & 3) * 4;            // 0,4,8,12
    const int b_kr0  = tid >> 5;                 // 0..7
    const int b_kr1  = b_kr0 + 8;
    const int b_cq   = (tid & 31) * 4;           // 0..124

    float acc[8][8];
    #pragma unroll
    for (int i = 0; i < 8; i++)
        #pragma unroll
        for (int j = 0; j < 8; j++) acc[i][j] = 0.f;

    const int tx4 = (tid & 15) * 4;              // col group 0: [tx4, tx4+4)
    const int ty  = (tid >> 4) * 8;              // col group 1: [tx4+64, tx4+68)

    float4 ra0, ra1, rb0, rb1;

    ra0 = *(const float4*)(Ab + (size_t)a_row0 * INDIM + a_kq);
    ra1 = *(const float4*)(Ab + (size_t)a_row1 * INDIM + a_kq);
    rb0 = *(const float4*)(Bb + (size_t)b_kr0 * N + b_cq);
    rb1 = *(const float4*)(Bb + (size_t)b_kr1 * N + b_cq);
    As[0][a_kq + 0][a_row0] = ra0.x; As[0][a_kq + 1][a_row0] = ra0.y;
    As[0][a_kq + 2][a_row0] = ra0.z; As[0][a_kq + 3][a_row0] = ra0.w;
    As[0][a_kq + 0][a_row1] = ra1.x; As[0][a_kq + 1][a_row1] = ra1.y;
    As[0][a_kq + 2][a_row1] = ra1.z; As[0][a_kq + 3][a_row1] = ra1.w;
    *(float4*)&Bs[0][b_kr0][b_cq] = rb0;
    *(float4*)&Bs[0][b_kr1][b_cq] = rb1;
    __syncthreads();

    const int ntiles = K / 16;
    for (int t = 0; t < ntiles; t++) {
        const int cur = t & 1;
        if (t + 1 < ntiles) {
            const int k0 = (t + 1) * 16;
            ra0 = *(const float4*)(Ab + (size_t)a_row0 * INDIM + k0 + a_kq);
            ra1 = *(const float4*)(Ab + (size_t)a_row1 * INDIM + k0 + a_kq);
            rb0 = *(const float4*)(Bb + (size_t)(k0 + b_kr0) * N + b_cq);
            rb1 = *(const float4*)(Bb + (size_t)(k0 + b_kr1) * N + b_cq);
        }

        #pragma unroll
        for (int kk = 0; kk < 16; kk++) {
            float a[8], b[8];
            *(float4*)(a)     = *(float4*)&As[cur][kk][ty];
            *(float4*)(a + 4) = *(float4*)&As[cur][kk][ty + 4];
            *(float4*)(b)     = *(float4*)&Bs[cur][kk][tx4];        // conflict-free
            *(float4*)(b + 4) = *(float4*)&Bs[cur][kk][tx4 + 64];   // conflict-free
            #pragma unroll
            for (int i = 0; i < 8; i++)
                #pragma unroll
                for (int j = 0; j < 8; j++) acc[i][j] += a[i] * b[j];
        }

        if (t + 1 < ntiles) {
            const int nxt = cur ^ 1;
            As[nxt][a_kq + 0][a_row0] = ra0.x; As[nxt][a_kq + 1][a_row0] = ra0.y;
            As[nxt][a_kq + 2][a_row0] = ra0.z; As[nxt][a_kq + 3][a_row0] = ra0.w;
            As[nxt][a_kq + 0][a_row1] = ra1.x; As[nxt][a_kq + 1][a_row1] = ra1.y;
            As[nxt][a_kq + 2][a_row1] = ra1.z; As[nxt][a_kq + 3][a_row1] = ra1.w;
            *(float4*)&Bs[nxt][b_kr0][b_cq] = rb0;
            *(float4*)&Bs[nxt][b_kr1][b_cq] = rb1;
            __syncthreads();
        }
    }

    #pragma unroll
    for (int i = 0; i < 8; i++) {
        float* Cp = g_q + (size_t)(blockIdx.y * 128 + ty + i) * N + blockIdx.x * 128;
        *(float4*)(Cp + tx4)      = make_float4(acc[i][0], acc[i][1], acc[i][2], acc[i][3]);
        *(float4*)(Cp + tx4 + 64) = make_float4(acc[i][4], acc[i][5], acc[i][6], acc[i][7]);
    }
}

// ============================================================================
// Kernel 2: scores[hs][b][n] = sum_d q[b, hs*256+d] * keys[hs][n][d]  (NT)
//   per hs: M=4096, N=512, K=256. grid=(4,32,8). Same 4+4 B-fragment split.
// ============================================================================
__global__ void __launch_bounds__(256, 2) score_gemm(const float* __restrict__ keys) {
    const int hs = blockIdx.z;
    const float* Ab = g_q + hs * HALF + (size_t)blockIdx.y * 128 * QCOLS;
    const float* Bb = keys + (size_t)hs * NKEYS * HALF + (size_t)blockIdx.x * 128 * HALF;
    float* Cb = g_scores + (size_t)hs * BSZ * NKEYS;

    __shared__ float As[2][16][128];
    __shared__ float Bs[2][16][128];

    const int tid = threadIdx.x;
    const int a_row0 = tid >> 2;
    const int a_row1 = a_row0 + 64;
    const int a_kq   = (tid & 3) * 4;

    float acc[8][8];
    #pragma unroll
    for (int i = 0; i < 8; i++)
        #pragma unroll
        for (int j = 0; j < 8; j++) acc[i][j] = 0.f;

    const int tx4 = (tid & 15) * 4;
    const int ty  = (tid >> 4) * 8;

    float4 ra0, ra1, rb0, rb1;

    ra0 = *(const float4*)(Ab + (size_t)a_row0 * QCOLS + a_kq);
    ra1 = *(const float4*)(Ab + (size_t)a_row1 * QCOLS + a_kq);
    rb0 = *(const float4*)(Bb + (size_t)a_row0 * HALF + a_kq);
    rb1 = *(const float4*)(Bb + (size_t)a_row1 * HALF + a_kq);
    As[0][a_kq + 0][a_row0] = ra0.x; As[0][a_kq + 1][a_row0] = ra0.y;
    As[0][a_kq + 2][a_row0] = ra0.z; As[0][a_kq + 3][a_row0] = ra0.w;
    As[0][a_kq + 0][a_row1] = ra1.x; As[0][a_kq + 1][a_row1] = ra1.y;
    As[0][a_kq + 2][a_row1] = ra1.z; As[0][a_kq + 3][a_row1] = ra1.w;
    Bs[0][a_kq + 0][a_row0] = rb0.x; Bs[0][a_kq + 1][a_row0] = rb0.y;
    Bs[0][a_kq + 2][a_row0] = rb0.z; Bs[0][a_kq + 3][a_row0] = rb0.w;
    Bs[0][a_kq + 0][a_row1] = rb1.x; Bs[0][a_kq + 1][a_row1] = rb1.y;
    Bs[0][a_kq + 2][a_row1] = rb1.z; Bs[0][a_kq + 3][a_row1] = rb1.w;
    __syncthreads();

    const int ntiles = HALF / 16;
    for (int t = 0; t < ntiles; t++) {
        const int cur = t & 1;
        if (t + 1 < ntiles) {
            const int k0 = (t + 1) * 16;
            ra0 = *(const float4*)(Ab + (size_t)a_row0 * QCOLS + k0 + a_kq);
            ra1 = *(const float4*)(Ab + (size_t)a_row1 * QCOLS + k0 + a_kq);
            rb0 = *(const float4*)(Bb + (size_t)a_row0 * HALF + k0 + a_kq);
            rb1 = *(const float4*)(Bb + (size_t)a_row1 * HALF + k0 + a_kq);
        }

        #pragma unroll
        for (int kk = 0; kk < 16; kk++) {
            float a[8], b[8];
            *(float4*)(a)     = *(float4*)&As[cur][kk][ty];
            *(float4*)(a + 4) = *(float4*)&As[cur][kk][ty + 4];
            *(float4*)(b)     = *(float4*)&Bs[cur][kk][tx4];
            *(float4*)(b + 4) = *(float4*)&Bs[cur][kk][tx4 + 64];
            #pragma unroll
            for (int i = 0; i < 8; i++)
                #pragma unroll
                for (int j = 0; j < 8; j++) acc[i][j] += a[i] * b[j];
        }

        if (t + 1 < ntiles) {
            const int nxt = cur ^ 1;
            As[nxt][a_kq + 0][a_row0] = ra0.x; As[nxt][a_kq + 1][a_row0] = ra0.y;
            As[nxt][a_kq + 2][a_row0] = ra0.z; As[nxt][a_kq + 3][a_row0] = ra0.w;
            As[nxt][a_kq + 0][a_row1] = ra1.x; As[nxt][a_kq + 1][a_row1] = ra1.y;
            As[nxt][a_kq + 2][a_row1] = ra1.z; As[nxt][a_kq + 3][a_row1] = ra1.w;
            Bs[nxt][a_kq + 0][a_row0] = rb0.x; Bs[nxt][a_kq + 1][a_row0] = rb0.y;
            Bs[nxt][a_kq + 2][a_row0] = rb0.z; Bs[nxt][a_kq + 3][a_row0] = rb0.w;
            Bs[nxt][a_kq + 0][a_row1] = rb1.x; Bs[nxt][a_kq + 1][a_row1] = rb1.y;
            Bs[nxt][a_kq + 2][a_row1] = rb1.z; Bs[nxt][a_kq + 3][a_row1] = rb1.w;
            __syncthreads();
        }
    }

    #pragma unroll
    for (int i = 0; i < 8; i++) {
        float* Cp = Cb + (size_t)(blockIdx.y * 128 + ty + i) * NKEYS + blockIdx.x * 128;
        *(float4*)(Cp + tx4)      = make_float4(acc[i][0], acc[i][1], acc[i][2], acc[i][3]);
        *(float4*)(Cp + tx4 + 64) = make_float4(acc[i][4], acc[i][5], acc[i][6], acc[i][7]);
    }
}

// ============================================================================
// Kernel 3: per-(b,h) top-k + cartesian top-k + softmax (R5 verbatim)
// ============================================================================
__global__ void __launch_bounds__(128) topk_kernel() {
    const int b    = blockIdx.x;
    const int h    = threadIdx.x >> 5;
    const int lane = threadIdx.x & 31;

    __shared__ float sv[HEADS][2][KNN];
    __shared__ int   si[HEADS][2][KNN];
    __shared__ float sbest[HEADS][KNN];
    __shared__ int   sbf[HEADS][KNN];

    #pragma unroll
    for (int s = 0; s < 2; s++) {
        const float* p = g_scores + ((size_t)(h * 2 + s)) * BSZ * NKEYS + (size_t)b * NKEYS;
        float v[16];
        #pragma unroll
        for (int j = 0; j < 16; j++) v[j] = p[j * 32 + lane];

        for (int r = 0; r < KNN; r++) {
            float bv = -1e30f; int bi = 1 << 30;
            #pragma unroll
            for (int j = 0; j < 16; j++) {
                if (v[j] > bv) { bv = v[j]; bi = j * 32 + lane; }
            }
            #pragma unroll
            for (int off = 16; off; off >>= 1) {
                float ov = __shfl_xor_sync(0xffffffffu, bv, off);
                int   oi = __shfl_xor_sync(0xffffffffu, bi, off);
                if (ov > bv || (ov == bv && oi < bi)) { bv = ov; bi = oi; }
            }
            if ((bi & 31) == lane) {
                int rem = bi >> 5;
                #pragma unroll
                for (int j = 0; j < 16; j++) if (j == rem) v[j] = -1e30f;
            }
            if (lane == 0) { sv[h][s][r] = bv; si[h][s][r] = bi; }
        }
    }
    __syncwarp();

    float cv[KNN];
    float s1l = sv[h][0][lane];
    #pragma unroll
    for (int j = 0; j < KNN; j++) cv[j] = s1l + sv[h][1][j];

    for (int r = 0; r < KNN; r++) {
        float bv = -1e30f; int bf = 1 << 30;
        #pragma unroll
        for (int j = 0; j < KNN; j++) {
            if (cv[j] > bv) { bv = cv[j]; bf = lane * 32 + j; }
        }
        #pragma unroll
        for (int off = 16; off; off >>= 1) {
            float ov = __shfl_xor_sync(0xffffffffu, bv, off);
            int   oi = __shfl_xor_sync(0xffffffffu, bf, off);
            if (ov > bv || (ov == bv && oi < bf)) { bv = ov; bf = oi; }
        }
        if ((bf >> 5) == lane) {
            int rem = bf & 31;
            #pragma unroll
            for (int j = 0; j < KNN; j++) if (j == rem) cv[j] = -1e30f;
        }
        if (lane == 0) { sbest[h][r] = bv; sbf[h][r] = bf; }
    }
    __syncwarp();

    float m = sbest[h][0];
    float e = expf(sbest[h][lane] - m);
    float sum = e;
    #pragma unroll
    for (int off = 16; off; off >>= 1) sum += __shfl_xor_sync(0xffffffffu, sum, off);
    float wgt = e / sum;

    int f = sbf[h][lane];
    int index = si[h][0][f >> 5] * NKEYS + si[h][1][f & 31];

    g_w  [(size_t)(b * HEADS + h) * KNN + lane] = wgt;
    g_idx[(size_t)(b * HEADS + h) * KNN + lane] = index;
}

// ============================================================================
// Kernel 4: gather + weighted sum (R5 verbatim: regs=32, occ 92%, 88% DRAM)
// ============================================================================
__global__ void __launch_bounds__(256) gather_kernel(const float* __restrict__ values,
                                                     float* __restrict__ out) {
    const int b = blockIdx.x;
    const int t = threadIdx.x;
    __shared__ float ws[HEADS * KNN];
    __shared__ int   is[HEADS * KNN];
    if (t < HEADS * KNN) {
        ws[t] = g_w[(size_t)b * HEADS * KNN + t];
        is[t] = g_idx[(size_t)b * HEADS * KNN + t];
    }
    __syncthreads();

    const float4* V = (const float4*)values;
    float4 acc = make_float4(0.f, 0.f, 0.f, 0.f);

    #pragma unroll 8
    for (int k = 0; k < HEADS * KNN; k++) {
        float w = ws[k];
        size_t row = (size_t)is[k];
        float4 v = V[row * (VDIM / 4) + t];
        acc.x += w * v.x; acc.y += w * v.y;
        acc.z += w * v.z; acc.w += w * v.w;
    }
    ((float4*)out)[(size_t)b * (VDIM / 4) + t] = acc;
}

// ============================================================================
extern "C" void kernel_launch(void* const* d_in, const int* in_sizes, int n_in,
                              void* d_out, int out_size) {
    const float* x      = (const float*)d_in[0];   // (4096, 1024)
    const float* wq     = (const float*)d_in[1];   // (1024, 2048)
    const float* keys   = (const float*)d_in[2];   // (4, 2, 512, 256)
    const float* values = (const float*)d_in[3];   // (262144, 1024)
    float* out = (float*)d_out;                    // (4096, 1024)

    {
        dim3 grid(QCOLS / 128, BSZ / 128);  // (16, 32)
        q_gemm<<<grid, 256>>>(x, wq);
    }
    {
        dim3 grid(NKEYS / 128, BSZ / 128, 8);  // (4, 32, 8)
        score_gemm<<<grid, 256>>>(keys);
    }
    topk_kernel<<<BSZ, 128>>>();
    gather_kernel<<<BSZ, 256>>>(values, out);
}